// round 9
// baseline (speedup 1.0000x reference)
#include <cuda_runtime.h>
#include <cuda_fp16.h>

// BilateralSliceApply on GB300 — Round 8.
// grid (4,16,16,8,12) f32, guide (4,1024,1024), inp/out (4,1024,1024,3).
//
// R4's 3xLDS.64 tap loads are provably bank-conflict-free (word = 3*idx+j,
// gcd(3,16)=1 -> 16 distinct bank pairs); R6/R7's LDS.128 variant aliased.
// R8 = R4 inner loop verbatim + 2 rows/block (prologue amortization +
// cross-row ILP) + launch_bounds(256,6) occupancy cap (clean test, unlike
// R5 which also serialized the epilogue) + streaming cache hints.

#define GH 16
#define GW 16
#define GD 8
#define HH 1024
#define WW 1024
#define TPB 256
#define NXS 18               // 16 x cells + halo each side (xbase = -1)
#define RPB 2                // rows per block
#define PLANE3 (NXS * GD * 3)  // 432 uint2 per row plane

__device__ __forceinline__ __half2 u2h(unsigned v) {
    __half2 h; asm("mov.b32 %0, %1;" : "=r"(*(unsigned*)&h) : "r"(v)); return h;
}

__global__ void __launch_bounds__(TPB, 6) bsa_kernel(
    const float* __restrict__ grid,
    const float* __restrict__ guide,
    const float* __restrict__ inp,
    float* __restrict__ out)
{
    __shared__ uint2 PY[RPB * PLANE3];   // 6.75 KB, [r][xi][z][c4] fp16

    const int y0  = blockIdx.x * RPB;
    const int b   = blockIdx.y;
    const int tid = threadIdx.x;
    const int x0  = tid * 4;

    // ---- prefetch row 0 pixel data (streaming: read once) ----
    const size_t row0 = (size_t)(b * HH + y0) * WW;
    float4 g4n = __ldcs(reinterpret_cast<const float4*>(guide + row0) + tid);
    const float4* ib0 = reinterpret_cast<const float4*>(inp + row0 * 3);
    float4 ian = __ldcs(ib0 + tid * 3 + 0);
    float4 ibn = __ldcs(ib0 + tid * 3 + 1);
    float4 icn = __ldcs(ib0 + tid * 3 + 2);

    // ---- stage RPB fp16 PY planes (y-interp hoisted) ----
    #pragma unroll
    for (int e = tid; e < RPB * PLANE3; e += TPB) {
        const int c4 = e % 3;
        int q = e / 3;
        const int z  = q & (GD - 1);  q >>= 3;
        const int xi = q % NXS;
        const int r  = q / NXS;
        const int gx = min(max(xi - 1, 0), GW - 1);

        const int vy = 2 * (y0 + r) - 63;
        const int fy = vy >> 7;
        const float wy1 = (float)(vy & 127) * (1.0f / 128.0f);
        const float wy0 = 1.0f - wy1;
        const int cy0 = min(max(fy,     0), GH - 1);
        const int cy1 = min(max(fy + 1, 0), GH - 1);

        const float4* g0 = reinterpret_cast<const float4*>(grid)
            + (size_t)(((b * GH + cy0) * GW + gx) * GD + z) * 3 + c4;
        const float4* g1 = reinterpret_cast<const float4*>(grid)
            + (size_t)(((b * GH + cy1) * GW + gx) * GD + z) * 3 + c4;
        const float4 a  = __ldg(g0);
        const float4 bb = __ldg(g1);
        const __half2 h0 = __floats2half2_rn(wy0 * a.x + wy1 * bb.x,
                                             wy0 * a.y + wy1 * bb.y);
        const __half2 h1 = __floats2half2_rn(wy0 * a.z + wy1 * bb.z,
                                             wy0 * a.w + wy1 * bb.w);
        uint2 v;
        v.x = *(const unsigned*)&h0;
        v.y = *(const unsigned*)&h1;
        PY[e] = v;
    }
    __syncthreads();

    // ---- x taps: cell uniform over the thread's 4 px, row-invariant ----
    const int vx = 2 * x0 - 63;
    const int fx = vx >> 7;
    const float wx1base = (float)(vx & 127) * (1.0f / 128.0f);
    const int ebr = (fx + 1) * (GD * 3);   // x-cell base within a plane (uint2 units)

    #pragma unroll
    for (int r = 0; r < RPB; r++) {
        const float4 g4 = g4n;
        const float4 ia = ian;
        const float4 ib = ibn;
        const float4 ic = icn;

        if (r + 1 < RPB) {   // prefetch next row
            const size_t rn = (size_t)(b * HH + y0 + r + 1) * WW;
            g4n = __ldcs(reinterpret_cast<const float4*>(guide + rn) + tid);
            const float4* ibp = reinterpret_cast<const float4*>(inp + rn * 3);
            ian = __ldcs(ibp + tid * 3 + 0);
            ibn = __ldcs(ibp + tid * 3 + 1);
            icn = __ldcs(ibp + tid * 3 + 2);
        }

        const int ebase0 = r * PLANE3 + ebr;
        const int ebase1 = ebase0 + GD * 3;
        const float gin[4] = {g4.x, g4.y, g4.z, g4.w};
        float o[12];

        #pragma unroll
        for (int p = 0; p < 4; p++) {
            const float wx1 = wx1base + (float)p * (2.0f / 128.0f);
            const float wx0 = 1.0f - wx1;

            const float tz = fmaf(gin[p], (float)GD, -0.5f);
            const float fz = floorf(tz);
            const float wz1 = tz - fz;
            const float wz0 = 1.0f - wz1;
            const int iz = (int)fz;
            const int z0 = min(max(iz,     0), GD - 1);
            const int z1 = min(max(iz + 1, 0), GD - 1);

            const __half2 W00 = __float2half2_rn(wx0 * wz0);
            const __half2 W01 = __float2half2_rn(wx0 * wz1);
            const __half2 W10 = __float2half2_rn(wx1 * wz0);
            const __half2 W11 = __float2half2_rn(wx1 * wz1);

            const int e00 = ebase0 + z0 * 3;
            const int e01 = ebase0 + z1 * 3;
            const int e10 = ebase1 + z0 * 3;
            const int e11 = ebase1 + z1 * 3;

            __half2 a0 = __float2half2_rn(0.f), a1 = a0, a2 = a0,
                    a3 = a0, a4 = a0, a5 = a0;
            {
                const uint2 q0 = PY[e00], q1 = PY[e00 + 1], q2 = PY[e00 + 2];
                a0 = __hfma2(u2h(q0.x), W00, a0); a1 = __hfma2(u2h(q0.y), W00, a1);
                a2 = __hfma2(u2h(q1.x), W00, a2); a3 = __hfma2(u2h(q1.y), W00, a3);
                a4 = __hfma2(u2h(q2.x), W00, a4); a5 = __hfma2(u2h(q2.y), W00, a5);
            }
            {
                const uint2 q0 = PY[e01], q1 = PY[e01 + 1], q2 = PY[e01 + 2];
                a0 = __hfma2(u2h(q0.x), W01, a0); a1 = __hfma2(u2h(q0.y), W01, a1);
                a2 = __hfma2(u2h(q1.x), W01, a2); a3 = __hfma2(u2h(q1.y), W01, a3);
                a4 = __hfma2(u2h(q2.x), W01, a4); a5 = __hfma2(u2h(q2.y), W01, a5);
            }
            {
                const uint2 q0 = PY[e10], q1 = PY[e10 + 1], q2 = PY[e10 + 2];
                a0 = __hfma2(u2h(q0.x), W10, a0); a1 = __hfma2(u2h(q0.y), W10, a1);
                a2 = __hfma2(u2h(q1.x), W10, a2); a3 = __hfma2(u2h(q1.y), W10, a3);
                a4 = __hfma2(u2h(q2.x), W10, a4); a5 = __hfma2(u2h(q2.y), W10, a5);
            }
            {
                const uint2 q0 = PY[e11], q1 = PY[e11 + 1], q2 = PY[e11 + 2];
                a0 = __hfma2(u2h(q0.x), W11, a0); a1 = __hfma2(u2h(q0.y), W11, a1);
                a2 = __hfma2(u2h(q1.x), W11, a2); a3 = __hfma2(u2h(q1.y), W11, a3);
                a4 = __hfma2(u2h(q2.x), W11, a4); a5 = __hfma2(u2h(q2.y), W11, a5);
            }

            const float c0 = __low2float(a0), c1 = __high2float(a0);
            const float c2 = __low2float(a1), c3 = __high2float(a1);
            const float c4 = __low2float(a2), c5 = __high2float(a2);
            const float c6 = __low2float(a3), c7 = __high2float(a3);
            const float c8 = __low2float(a4), c9 = __high2float(a4);
            const float cA = __low2float(a5), cB = __high2float(a5);

            float i0, i1, i2;
            if (p == 0)      { i0 = ia.x; i1 = ia.y; i2 = ia.z; }
            else if (p == 1) { i0 = ia.w; i1 = ib.x; i2 = ib.y; }
            else if (p == 2) { i0 = ib.z; i1 = ib.w; i2 = ic.x; }
            else             { i0 = ic.y; i1 = ic.z; i2 = ic.w; }

            o[3 * p + 0] = c0 * i0 + c1 * i1 + c2 * i2 + c3;
            o[3 * p + 1] = c4 * i0 + c5 * i1 + c6 * i2 + c7;
            o[3 * p + 2] = c8 * i0 + c9 * i1 + cA * i2 + cB;
        }

        // batched epilogue stores, streaming (never re-read)
        float4* obase = reinterpret_cast<float4*>(
            out + (size_t)(b * HH + y0 + r) * WW * 3);
        __stcs(obase + tid * 3 + 0, make_float4(o[0], o[1], o[2],  o[3]));
        __stcs(obase + tid * 3 + 1, make_float4(o[4], o[5], o[6],  o[7]));
        __stcs(obase + tid * 3 + 2, make_float4(o[8], o[9], o[10], o[11]));
    }
}

extern "C" void kernel_launch(void* const* d_in, const int* in_sizes, int n_in,
                              void* d_out, int out_size)
{
    const float* grid  = (const float*)d_in[0];
    const float* guide = (const float*)d_in[1];
    const float* inp   = (const float*)d_in[2];
    float* out = (float*)d_out;

    const int B = in_sizes[1] / (HH * WW);  // 4

    dim3 blk(TPB, 1, 1);
    dim3 grd(HH / RPB, B, 1);               // (512, 4)
    bsa_kernel<<<grd, blk>>>(grid, guide, inp, out);
}